// round 13
// baseline (speedup 1.0000x reference)
#include <cuda_runtime.h>
#include <cstdint>

// Sinkhorn on B x 64 x 64 matrices, scaling-vector form, one warp per matrix,
// one 32-thread CTA per matrix. K frozen in registers (12 warps/SM ceiling).
// XOR-permuted data placement: lane stores row pair k at local slot k^tj and
// col pack p at local slot p^bitrev(ti), making both reduce-scatters UNIFORM
// (no selects) and all allgathers immediate-mask xor-shuffles.

typedef unsigned long long u64;
#define FULLMASK 0xffffffffu

__device__ __forceinline__ u64 pk2(float lo, float hi){
    u64 r; asm("mov.b64 %0, {%1, %2};" : "=l"(r) : "f"(lo), "f"(hi)); return r;
}
__device__ __forceinline__ void up2(u64 p, float& lo, float& hi){
    asm("mov.b64 {%0, %1}, %2;" : "=f"(lo), "=f"(hi) : "l"(p));
}
__device__ __forceinline__ u64 addx2(u64 a, u64 b){
    u64 r; asm("add.rn.f32x2 %0, %1, %2;" : "=l"(r) : "l"(a), "l"(b)); return r;
}
__device__ __forceinline__ u64 mulx2(u64 a, u64 b){
    u64 r; asm("mul.rn.f32x2 %0, %1, %2;" : "=l"(r) : "l"(a), "l"(b)); return r;
}
__device__ __forceinline__ u64 fmax2(u64 a, u64 b, u64 c){
    u64 r; asm("fma.rn.f32x2 %0, %1, %2, %3;" : "=l"(r) : "l"(a), "l"(b), "l"(c)); return r;
}
__device__ __forceinline__ float frcp(float x){
    float r; asm("rcp.approx.f32 %0, %1;" : "=f"(r) : "f"(x)); return r;
}
__device__ __forceinline__ float fex2(float x){
    float r; asm("ex2.approx.f32 %0, %1;" : "=f"(r) : "f"(x)); return r;
}
__device__ __forceinline__ u64 shfl64(u64 v, int m){
    return __shfl_xor_sync(FULLMASK, v, m);
}
__device__ __forceinline__ u64 max2u(u64 A, u64 B){
    float a, b, c, d; up2(A, a, b); up2(B, c, d);
    return pk2(fmaxf(a, c), fmaxf(b, d));
}

// Precomputed softplus(-gamma) * (1/temp) * log2(e), shared by all batches.
__device__ float d_gp2[64 * 64];

__global__ void prep_kernel(const float* __restrict__ gamma){
    int i = blockIdx.x * blockDim.x + threadIdx.x;
    if (i < 64 * 64){
        float g = gamma[i];
        float sp = (g > 0.f) ? log1pf(expf(-g)) : (-g + log1pf(expf(g)));
        d_gp2[i] = sp * 14.4269504088896341f;   // * 10 (1/temp) * log2(e)
    }
}

__global__ void __launch_bounds__(32, 12) sinkhorn_kernel(
        const float* __restrict__ noise, float* __restrict__ out){
    int gw = blockIdx.x;                        // matrix id (grid = B)
    int lane = threadIdx.x;
    int tj = lane & 7;        // column group (8 groups of 8 cols)
    int ti = lane >> 3;       // row group    (4 groups of 16 rows)
    int row0 = ti * 16, col0 = tj * 8;
    int f = ((ti & 1) << 1) | (ti >> 1);        // 2-bit reverse of ti
    int o1 = (f & 2) ? 4 : 0;                   // f bit1 via load pointers
    int o2 = 4 - o1;
    bool s1 = (f & 1) != 0;                     // f bit0 via pack selects

    const float* np = noise + ((size_t)gw * 64 + row0) * 64 + col0;
    const float* gp = d_gp2 + row0 * 64 + col0;
    const float KS = 14.4269504088896341f;      // 10 * log2(e)

    // K[2k+s][p]: local row pair k = global pair k^tj (rows row0+2(k^tj)+s),
    // local col pack p = global pack p^f (cols col0+2(p^f)+{0,1}).
    u64 K[16][4];
    float xm[16];

    // ---- load (permuted), scale into log2 domain, per-local-row max ----
    #pragma unroll
    for (int k = 0; k < 8; ++k){
        int gr = 2 * (k ^ tj);
        #pragma unroll
        for (int s = 0; s < 2; ++s){
            const float* pn = np + (size_t)(gr + s) * 64;
            const float* pg = gp + (gr + s) * 64;
            float4 nA = *(const float4*)(pn + o1);
            float4 nB = *(const float4*)(pn + o2);
            float4 gA = *(const float4*)(pg + o1);
            float4 gB = *(const float4*)(pg + o2);
            float x0 = fmaf(nA.x, KS, gA.x);
            float x1 = fmaf(nA.y, KS, gA.y);
            float x2 = fmaf(nA.z, KS, gA.z);
            float x3 = fmaf(nA.w, KS, gA.w);
            float x4 = fmaf(nB.x, KS, gB.x);
            float x5 = fmaf(nB.y, KS, gB.y);
            float x6 = fmaf(nB.z, KS, gB.z);
            float x7 = fmaf(nB.w, KS, gB.w);
            int r = 2 * k + s;
            u64 A0 = pk2(x0, x1), A1 = pk2(x2, x3);
            u64 B0 = pk2(x4, x5), B1 = pk2(x6, x7);
            K[r][0] = s1 ? A1 : A0;
            K[r][1] = s1 ? A0 : A1;
            K[r][2] = s1 ? B1 : B0;
            K[r][3] = s1 ? B0 : B1;
            xm[r] = fmaxf(fmaxf(fmaxf(x0, x1), fmaxf(x2, x3)),
                          fmaxf(fmaxf(x4, x5), fmaxf(x6, x7)));
        }
    }
    // ---- row-max: uniform packed max reduce-scatter over tj + xor allgather ----
    {
        u64 mp[8];
        #pragma unroll
        for (int k = 0; k < 8; ++k) mp[k] = pk2(xm[2 * k], xm[2 * k + 1]);
        #pragma unroll
        for (int k = 0; k < 4; ++k) mp[k] = max2u(mp[k], shfl64(mp[k + 4], 4));
        #pragma unroll
        for (int k = 0; k < 2; ++k) mp[k] = max2u(mp[k], shfl64(mp[k + 2], 2));
        mp[0] = max2u(mp[0], shfl64(mp[1], 1));
        #pragma unroll
        for (int k = 0; k < 8; ++k){
            u64 mk = k ? shfl64(mp[0], k) : mp[0];
            float ml, mh; up2(mk, ml, mh);
            u64 nl = pk2(-ml, -ml), nh = pk2(-mh, -mh);
            #pragma unroll
            for (int p = 0; p < 4; ++p){
                u64 t = addx2(K[2 * k][p], nl);
                float u, v; up2(t, u, v);
                K[2 * k][p] = pk2(fex2(u), fex2(v));
                t = addx2(K[2 * k + 1][p], nh);
                up2(t, u, v);
                K[2 * k + 1][p] = pk2(fex2(u), fex2(v));
            }
        }
    }

    // Iteration state (local orderings): c2[p] matches local col packs,
    // rv2[j] matches local row pairs.
    u64 c2[4];
    c2[0] = pk2(1.f, 1.f); c2[1] = c2[0]; c2[2] = c2[0]; c2[3] = c2[0];
    u64 rv2[8];

    #pragma unroll 1
    for (int it = 0; it < 50; ++it){
        // ---- row partial sums: single-chain per row, 16 independent chains ----
        u64 pr[8];
        #pragma unroll
        for (int k = 0; k < 8; ++k){
            int r0 = 2 * k, r1 = r0 + 1;
            u64 a0 = mulx2(K[r0][0], c2[0]);
            a0 = fmax2(K[r0][1], c2[1], a0);
            a0 = fmax2(K[r0][2], c2[2], a0);
            a0 = fmax2(K[r0][3], c2[3], a0);
            u64 a1 = mulx2(K[r1][0], c2[0]);
            a1 = fmax2(K[r1][1], c2[1], a1);
            a1 = fmax2(K[r1][2], c2[2], a1);
            a1 = fmax2(K[r1][3], c2[3], a1);
            float a, b, d, e;
            up2(a0, a, b); up2(a1, d, e);
            pr[k] = pk2(a + b, d + e);
        }
        // ---- UNIFORM reduce-scatter over tj (no selects) ----
        #pragma unroll
        for (int k = 0; k < 4; ++k) pr[k] = addx2(pr[k], shfl64(pr[k + 4], 4));
        #pragma unroll
        for (int k = 0; k < 2; ++k) pr[k] = addx2(pr[k], shfl64(pr[k + 2], 2));
        pr[0] = addx2(pr[0], shfl64(pr[1], 1));
        u64 own_rv;
        { float u, v; up2(pr[0], u, v); own_rv = pk2(frcp(u), frcp(v)); }
        // ---- allgather: owner of local pair j is lane^j ----
        rv2[0] = own_rv;
        #pragma unroll
        for (int j = 1; j < 8; ++j) rv2[j] = shfl64(own_rv, j);

        // ---- col partial sums over this lane's 16 rows (dual accumulators) ----
        u64 cpA[4], cpB[4];
        {
            float lo, hi; up2(rv2[0], lo, hi);
            u64 bl = pk2(lo, lo), bh = pk2(hi, hi);
            #pragma unroll
            for (int p = 0; p < 4; ++p)
                cpA[p] = fmax2(K[1][p], bh, mulx2(K[0][p], bl));
        }
        {
            float lo, hi; up2(rv2[4], lo, hi);
            u64 bl = pk2(lo, lo), bh = pk2(hi, hi);
            #pragma unroll
            for (int p = 0; p < 4; ++p)
                cpB[p] = fmax2(K[9][p], bh, mulx2(K[8][p], bl));
        }
        #pragma unroll
        for (int j = 1; j < 4; ++j){
            float lo, hi; up2(rv2[j], lo, hi);
            u64 bl = pk2(lo, lo), bh = pk2(hi, hi);
            float lo2, hi2; up2(rv2[j + 4], lo2, hi2);
            u64 bl2 = pk2(lo2, lo2), bh2 = pk2(hi2, hi2);
            #pragma unroll
            for (int p = 0; p < 4; ++p){
                cpA[p] = fmax2(K[2 * j][p],     bl,  cpA[p]);
                cpA[p] = fmax2(K[2 * j + 1][p], bh,  cpA[p]);
                cpB[p] = fmax2(K[2 * j + 8][p], bl2, cpB[p]);
                cpB[p] = fmax2(K[2 * j + 9][p], bh2, cpB[p]);
            }
        }
        u64 cp[4];
        #pragma unroll
        for (int p = 0; p < 4; ++p) cp[p] = addx2(cpA[p], cpB[p]);

        // ---- UNIFORM reduce-scatter over ti (xor8 then xor16, no selects) ----
        cp[0] = addx2(cp[0], shfl64(cp[2], 8));
        cp[1] = addx2(cp[1], shfl64(cp[3], 8));
        cp[0] = addx2(cp[0], shfl64(cp[1], 16));
        float u, v; up2(cp[0], u, v);
        u64 own_c = pk2(frcp(u), frcp(v));
        // ---- allgather: local pack p owner is lane ^ {0,16,8,24}[p] ----
        c2[0] = own_c;
        c2[1] = shfl64(own_c, 16);
        c2[2] = shfl64(own_c, 8);
        c2[3] = shfl64(own_c, 24);
    }

    // ---- materialize out = diag(r) K diag(c), store at permuted offsets ----
    float* op = out + ((size_t)gw * 64 + row0) * 64 + col0;
    int c0o = 2 * (0 ^ f), c1o = 2 * (1 ^ f), c2o = 2 * (2 ^ f), c3o = 2 * (3 ^ f);
    #pragma unroll
    for (int j = 0; j < 8; ++j){
        float lo, hi; up2(rv2[j], lo, hi);
        u64 bl = pk2(lo, lo), bh = pk2(hi, hi);
        int r0 = 2 * j, r1 = r0 + 1;
        int gr = 2 * (j ^ tj);
        float* ra = op + (size_t)gr * 64;
        float* rb = ra + 64;
        *(u64*)(ra + c0o) = mulx2(mulx2(K[r0][0], bl), c2[0]);
        *(u64*)(ra + c1o) = mulx2(mulx2(K[r0][1], bl), c2[1]);
        *(u64*)(ra + c2o) = mulx2(mulx2(K[r0][2], bl), c2[2]);
        *(u64*)(ra + c3o) = mulx2(mulx2(K[r0][3], bl), c2[3]);
        *(u64*)(rb + c0o) = mulx2(mulx2(K[r1][0], bh), c2[0]);
        *(u64*)(rb + c1o) = mulx2(mulx2(K[r1][1], bh), c2[1]);
        *(u64*)(rb + c2o) = mulx2(mulx2(K[r1][2], bh), c2[2]);
        *(u64*)(rb + c3o) = mulx2(mulx2(K[r1][3], bh), c2[3]);
    }
}

extern "C" void kernel_launch(void* const* d_in, const int* in_sizes, int n_in,
                              void* d_out, int out_size) {
    const float* gamma = (const float*)d_in[0];   // [64,64] fp32
    const float* noise = (const float*)d_in[1];   // [B,64,64] fp32
    float* out = (float*)d_out;                   // [B,64,64] fp32
    int B = in_sizes[1] / (64 * 64);

    prep_kernel<<<16, 256>>>(gamma);
    sinkhorn_kernel<<<B, 32>>>(noise, out);       // one 32-thread CTA per matrix
}

// round 14
// speedup vs baseline: 1.1005x; 1.1005x over previous
#include <cuda_runtime.h>
#include <cstdint>

// Sinkhorn on B x 64 x 64 matrices, scaling-vector form, one warp per matrix,
// one 32-thread CTA per matrix. K frozen in registers (12 warps/SM ceiling).
// XOR-permuted register placement (uniform select-free reduce-scatters, from
// R13) with COALESCED memory: noise permuted via a swizzled smem staging tile,
// gamma via a pre-permuted lane-interleaved table, epilogue staged back.

typedef unsigned long long u64;
#define FULLMASK 0xffffffffu

__device__ __forceinline__ u64 pk2(float lo, float hi){
    u64 r; asm("mov.b64 %0, {%1, %2};" : "=l"(r) : "f"(lo), "f"(hi)); return r;
}
__device__ __forceinline__ void up2(u64 p, float& lo, float& hi){
    asm("mov.b64 {%0, %1}, %2;" : "=f"(lo), "=f"(hi) : "l"(p));
}
__device__ __forceinline__ u64 addx2(u64 a, u64 b){
    u64 r; asm("add.rn.f32x2 %0, %1, %2;" : "=l"(r) : "l"(a), "l"(b)); return r;
}
__device__ __forceinline__ u64 mulx2(u64 a, u64 b){
    u64 r; asm("mul.rn.f32x2 %0, %1, %2;" : "=l"(r) : "l"(a), "l"(b)); return r;
}
__device__ __forceinline__ u64 fmax2(u64 a, u64 b, u64 c){
    u64 r; asm("fma.rn.f32x2 %0, %1, %2, %3;" : "=l"(r) : "l"(a), "l"(b), "l"(c)); return r;
}
__device__ __forceinline__ float frcp(float x){
    float r; asm("rcp.approx.f32 %0, %1;" : "=f"(r) : "f"(x)); return r;
}
__device__ __forceinline__ float fex2(float x){
    float r; asm("ex2.approx.f32 %0, %1;" : "=f"(r) : "f"(x)); return r;
}
__device__ __forceinline__ u64 shfl64(u64 v, int m){
    return __shfl_xor_sync(FULLMASK, v, m);
}
__device__ __forceinline__ u64 max2u(u64 A, u64 B){
    float a, b, c, d; up2(A, a, b); up2(B, c, d);
    return pk2(fmaxf(a, c), fmaxf(b, d));
}

// Pre-permuted, lane-interleaved softplus(-gamma)*10*log2(e) table.
// Entry [e*32 + lane], e = 4k + 2s + which, holds the 4 gamma values that the
// kernel adds into K[2k+s][2*which + {0,1}] (already in local-pack order).
__device__ float4 d_gtab[1024];

__global__ void prep_kernel(const float* __restrict__ gamma){
    int t = blockIdx.x * blockDim.x + threadIdx.x;
    if (t < 1024){
        int lane = t & 31, e = t >> 5;
        int k = e >> 2, s = (e >> 1) & 1, which = e & 1;
        int tj = lane & 7, ti = lane >> 3;
        int f = ((ti & 1) << 1) | (ti >> 1);       // 2-bit reverse of ti
        int rg = 16 * ti + 2 * (k ^ tj) + s;        // global row
        int base = 8 * tj;
        int p0 = (2 * which) ^ f, p1 = (2 * which + 1) ^ f;  // global packs
        int c0 = base + 2 * p0, c1 = base + 2 * p1;
        const float KS = 14.4269504088896341f;
        float g;
        float4 o;
        g = gamma[rg * 64 + c0];
        o.x = ((g > 0.f) ? log1pf(expf(-g)) : (-g + log1pf(expf(g)))) * KS;
        g = gamma[rg * 64 + c0 + 1];
        o.y = ((g > 0.f) ? log1pf(expf(-g)) : (-g + log1pf(expf(g)))) * KS;
        g = gamma[rg * 64 + c1];
        o.z = ((g > 0.f) ? log1pf(expf(-g)) : (-g + log1pf(expf(g)))) * KS;
        g = gamma[rg * 64 + c1 + 1];
        o.w = ((g > 0.f) ? log1pf(expf(-g)) : (-g + log1pf(expf(g)))) * KS;
        d_gtab[t] = o;
    }
}

__global__ void __launch_bounds__(32, 12) sinkhorn_kernel(
        const float* __restrict__ noise, float* __restrict__ out){
    // Staging tile in GLOBAL element order, column-float4 swizzled by row pair:
    // element (rg, c4) lives at tile[rg*16 + ((c4 + ((rg>>1)&7)) & 15)].
    __shared__ float4 tile[1024];                // 16 KB

    int gw = blockIdx.x;                          // matrix id (grid = B)
    int lane = threadIdx.x;
    int tj = lane & 7;
    int ti = lane >> 3;
    int f = ((ti & 1) << 1) | (ti >> 1);          // 2-bit reverse of ti
    int w = f >> 1;                               // = ti & 1
    bool s1 = (f & 1) != 0;                       // = ti >> 1
    const float KS = 14.4269504088896341f;        // 10 * log2(e)

    // ---- stage noise: linear coalesced loads -> swizzled smem ----
    const float4* nb = (const float4*)(noise + (size_t)gw * 4096);
    #pragma unroll
    for (int c = 0; c < 32; ++c){
        int idx = c * 32 + lane;
        int rg = idx >> 4, c4 = idx & 15;
        tile[rg * 16 + ((c4 + ((rg >> 1) & 7)) & 15)] = nb[idx];
    }
    __syncwarp();

    // K[2k+s][p]: local row pair k = global pair k^tj, local pack p = global p^f.
    u64 K[16][4];
    float xm[16];
    int c4a = 2 * tj + w, c4b = 2 * tj + 1 - w;

    #pragma unroll
    for (int k = 0; k < 8; ++k){
        int pg = k ^ tj;                          // global pair; also the swizzle key
        #pragma unroll
        for (int s = 0; s < 2; ++s){
            int rg = 16 * ti + 2 * pg + s;
            float4 nA = tile[rg * 16 + ((c4a + pg) & 15)];
            float4 nB = tile[rg * 16 + ((c4b + pg) & 15)];
            int e = (2 * k + s) * 2;
            float4 gA = d_gtab[e * 32 + lane];
            float4 gB = d_gtab[(e + 1) * 32 + lane];
            // s1 swap on the noise halves (gamma table is pre-swapped)
            float na0 = s1 ? nA.z : nA.x, na1 = s1 ? nA.w : nA.y;
            float na2 = s1 ? nA.x : nA.z, na3 = s1 ? nA.y : nA.w;
            float nb0 = s1 ? nB.z : nB.x, nb1 = s1 ? nB.w : nB.y;
            float nb2 = s1 ? nB.x : nB.z, nb3 = s1 ? nB.y : nB.w;
            float x0 = fmaf(na0, KS, gA.x);
            float x1 = fmaf(na1, KS, gA.y);
            float x2 = fmaf(na2, KS, gA.z);
            float x3 = fmaf(na3, KS, gA.w);
            float x4 = fmaf(nb0, KS, gB.x);
            float x5 = fmaf(nb1, KS, gB.y);
            float x6 = fmaf(nb2, KS, gB.z);
            float x7 = fmaf(nb3, KS, gB.w);
            int r = 2 * k + s;
            K[r][0] = pk2(x0, x1);
            K[r][1] = pk2(x2, x3);
            K[r][2] = pk2(x4, x5);
            K[r][3] = pk2(x6, x7);
            xm[r] = fmaxf(fmaxf(fmaxf(x0, x1), fmaxf(x2, x3)),
                          fmaxf(fmaxf(x4, x5), fmaxf(x6, x7)));
        }
    }
    // ---- row-max: uniform packed max reduce-scatter over tj + xor allgather ----
    {
        u64 mp[8];
        #pragma unroll
        for (int k = 0; k < 8; ++k) mp[k] = pk2(xm[2 * k], xm[2 * k + 1]);
        #pragma unroll
        for (int k = 0; k < 4; ++k) mp[k] = max2u(mp[k], shfl64(mp[k + 4], 4));
        #pragma unroll
        for (int k = 0; k < 2; ++k) mp[k] = max2u(mp[k], shfl64(mp[k + 2], 2));
        mp[0] = max2u(mp[0], shfl64(mp[1], 1));
        #pragma unroll
        for (int k = 0; k < 8; ++k){
            u64 mk = k ? shfl64(mp[0], k) : mp[0];
            float ml, mh; up2(mk, ml, mh);
            u64 nl = pk2(-ml, -ml), nh = pk2(-mh, -mh);
            #pragma unroll
            for (int p = 0; p < 4; ++p){
                u64 t = addx2(K[2 * k][p], nl);
                float u, v; up2(t, u, v);
                K[2 * k][p] = pk2(fex2(u), fex2(v));
                t = addx2(K[2 * k + 1][p], nh);
                up2(t, u, v);
                K[2 * k + 1][p] = pk2(fex2(u), fex2(v));
            }
        }
    }

    // Iteration state (local orderings).
    u64 c2[4];
    c2[0] = pk2(1.f, 1.f); c2[1] = c2[0]; c2[2] = c2[0]; c2[3] = c2[0];
    u64 rv2[8];

    #pragma unroll 1
    for (int it = 0; it < 50; ++it){
        // ---- row partial sums: single-chain per row, 16 independent chains ----
        u64 pr[8];
        #pragma unroll
        for (int k = 0; k < 8; ++k){
            int r0 = 2 * k, r1 = r0 + 1;
            u64 a0 = mulx2(K[r0][0], c2[0]);
            a0 = fmax2(K[r0][1], c2[1], a0);
            a0 = fmax2(K[r0][2], c2[2], a0);
            a0 = fmax2(K[r0][3], c2[3], a0);
            u64 a1 = mulx2(K[r1][0], c2[0]);
            a1 = fmax2(K[r1][1], c2[1], a1);
            a1 = fmax2(K[r1][2], c2[2], a1);
            a1 = fmax2(K[r1][3], c2[3], a1);
            float a, b, d, e;
            up2(a0, a, b); up2(a1, d, e);
            pr[k] = pk2(a + b, d + e);
        }
        // ---- UNIFORM reduce-scatter over tj (no selects) ----
        #pragma unroll
        for (int k = 0; k < 4; ++k) pr[k] = addx2(pr[k], shfl64(pr[k + 4], 4));
        #pragma unroll
        for (int k = 0; k < 2; ++k) pr[k] = addx2(pr[k], shfl64(pr[k + 2], 2));
        pr[0] = addx2(pr[0], shfl64(pr[1], 1));
        u64 own_rv;
        { float u, v; up2(pr[0], u, v); own_rv = pk2(frcp(u), frcp(v)); }
        // ---- allgather: owner of local pair j is lane^j ----
        rv2[0] = own_rv;
        #pragma unroll
        for (int j = 1; j < 8; ++j) rv2[j] = shfl64(own_rv, j);

        // ---- col partial sums over this lane's 16 rows (dual accumulators) ----
        u64 cpA[4], cpB[4];
        {
            float lo, hi; up2(rv2[0], lo, hi);
            u64 bl = pk2(lo, lo), bh = pk2(hi, hi);
            #pragma unroll
            for (int p = 0; p < 4; ++p)
                cpA[p] = fmax2(K[1][p], bh, mulx2(K[0][p], bl));
        }
        {
            float lo, hi; up2(rv2[4], lo, hi);
            u64 bl = pk2(lo, lo), bh = pk2(hi, hi);
            #pragma unroll
            for (int p = 0; p < 4; ++p)
                cpB[p] = fmax2(K[9][p], bh, mulx2(K[8][p], bl));
        }
        #pragma unroll
        for (int j = 1; j < 4; ++j){
            float lo, hi; up2(rv2[j], lo, hi);
            u64 bl = pk2(lo, lo), bh = pk2(hi, hi);
            float lo2, hi2; up2(rv2[j + 4], lo2, hi2);
            u64 bl2 = pk2(lo2, lo2), bh2 = pk2(hi2, hi2);
            #pragma unroll
            for (int p = 0; p < 4; ++p){
                cpA[p] = fmax2(K[2 * j][p],     bl,  cpA[p]);
                cpA[p] = fmax2(K[2 * j + 1][p], bh,  cpA[p]);
                cpB[p] = fmax2(K[2 * j + 8][p], bl2, cpB[p]);
                cpB[p] = fmax2(K[2 * j + 9][p], bh2, cpB[p]);
            }
        }
        u64 cp[4];
        #pragma unroll
        for (int p = 0; p < 4; ++p) cp[p] = addx2(cpA[p], cpB[p]);

        // ---- UNIFORM reduce-scatter over ti (xor8 then xor16, no selects) ----
        cp[0] = addx2(cp[0], shfl64(cp[2], 8));
        cp[1] = addx2(cp[1], shfl64(cp[3], 8));
        cp[0] = addx2(cp[0], shfl64(cp[1], 16));
        float u, v; up2(cp[0], u, v);
        u64 own_c = pk2(frcp(u), frcp(v));
        // ---- allgather: local pack p owner is lane ^ {0,16,8,24}[p] ----
        c2[0] = own_c;
        c2[1] = shfl64(own_c, 16);
        c2[2] = shfl64(own_c, 8);
        c2[3] = shfl64(own_c, 24);
    }

    // ---- materialize out = diag(r) K diag(c): swizzled smem stage, then
    //      linear coalesced stores ----
    __syncwarp();
    #pragma unroll
    for (int j = 0; j < 8; ++j){
        float lo, hi; up2(rv2[j], lo, hi);
        u64 bl = pk2(lo, lo), bh = pk2(hi, hi);
        int pg = j ^ tj;
        #pragma unroll
        for (int s = 0; s < 2; ++s){
            u64 sc = s ? bh : bl;
            int r = 2 * j + s;
            u64 P0 = mulx2(mulx2(K[r][0], sc), c2[0]);
            u64 P1 = mulx2(mulx2(K[r][1], sc), c2[1]);
            u64 P2 = mulx2(mulx2(K[r][2], sc), c2[2]);
            u64 P3 = mulx2(mulx2(K[r][3], sc), c2[3]);
            u64 A  = s1 ? P1 : P0, A2 = s1 ? P0 : P1;
            u64 Bq = s1 ? P3 : P2, B2 = s1 ? P2 : P3;
            int rg = 16 * ti + 2 * pg + s;
            float a0, a1, a2, a3;
            up2(A, a0, a1); up2(A2, a2, a3);
            tile[rg * 16 + ((c4a + pg) & 15)] = make_float4(a0, a1, a2, a3);
            up2(Bq, a0, a1); up2(B2, a2, a3);
            tile[rg * 16 + ((c4b + pg) & 15)] = make_float4(a0, a1, a2, a3);
        }
    }
    __syncwarp();
    float4* ob = (float4*)(out + (size_t)gw * 4096);
    #pragma unroll
    for (int c = 0; c < 32; ++c){
        int idx = c * 32 + lane;
        int rg = idx >> 4, c4 = idx & 15;
        ob[idx] = tile[rg * 16 + ((c4 + ((rg >> 1) & 7)) & 15)];
    }
}

extern "C" void kernel_launch(void* const* d_in, const int* in_sizes, int n_in,
                              void* d_out, int out_size) {
    const float* gamma = (const float*)d_in[0];   // [64,64] fp32
    const float* noise = (const float*)d_in[1];   // [B,64,64] fp32
    float* out = (float*)d_out;                   // [B,64,64] fp32
    int B = in_sizes[1] / (64 * 64);

    prep_kernel<<<4, 256>>>(gamma);
    sinkhorn_kernel<<<B, 32>>>(noise, out);       // one 32-thread CTA per matrix
}